// round 13
// baseline (speedup 1.0000x reference)
#include <cuda_runtime.h>
#include <math.h>

#define IMG_H 1080
#define IMG_W 1920
#define HW (IMG_H * IMG_W)
#define HW4 (HW / 4)
#define WBLK (IMG_W / 2)   // 960 blocks per block-row

// Scratch (no cudaMalloc allowed)
__device__ float4   g_buf4[HW];     // accumulated (r*w, g*w, b*w, z*w) per pixel
__device__ float    g_wplane[HW];   // accumulated w, 2x2-blocked layout:
                                    // idx(x,y) = ((y>>1)*WBLK + (x>>1))*4 + (y&1)*2 + (x&1)
__device__ unsigned g_zbuf[HW];     // z-buffer bits (positive floats: order-preserving)

__global__ void init_kernel() {
    int i = blockIdx.x * blockDim.x + threadIdx.x;
    if (i >= HW4) return;
    const float4 z4 = make_float4(0.f, 0.f, 0.f, 0.f);
    ((float4*)g_wplane)[i] = z4;
    ((uint4*)g_zbuf)[i] = make_uint4(0x7f800000u, 0x7f800000u, 0x7f800000u, 0x7f800000u);
    g_buf4[i]           = z4;
    g_buf4[i + HW4]     = z4;
    g_buf4[i + 2*HW4]   = z4;
    g_buf4[i + 3*HW4]   = z4;
}

// EXACT arithmetic (discrete decisions downstream: floor, z-compare).
__device__ __forceinline__ bool project(
    const float* __restrict__ vm, const float* __restrict__ Km,
    float mx, float my, float mz,
    float& x, float& y, float& z)
{
    z = vm[8] * mx + vm[9] * my + vm[10] * mz + vm[11];
    if (!(z > 0.1f)) return false;
    float cxm = vm[0] * mx + vm[1] * my + vm[2] * mz + vm[3];
    float cym = vm[4] * mx + vm[5] * my + vm[6] * mz + vm[7];
    float fx = Km[0], cx = Km[2], fy = Km[4], cy = Km[5];
    x = cxm * fx / z + cx;
    y = cym * fy / z + cy;
    return (x >= 0.f) & (x < (float)(IMG_W - 1)) & (y >= 0.f) & (y < (float)(IMG_H - 1));
}

__device__ __forceinline__ float sigmoidf(float v) {
    return 1.f / (1.f + expf(-v));
}

// ---------------------------------------------------------------------------
// Pass 1: per-pixel z-min via atomicMin on float bits.
// ---------------------------------------------------------------------------
__global__ void zmin_kernel(const float* __restrict__ means,
                            const float* __restrict__ vm,
                            const float* __restrict__ Km, int n)
{
    int i = blockIdx.x * blockDim.x + threadIdx.x;
    if (i >= n) return;
    float mx = means[3 * i], my = means[3 * i + 1], mz = means[3 * i + 2];
    float x, y, z;
    if (!project(vm, Km, mx, my, mz, x, y, z)) return;
    int x0 = (int)floorf(x);
    int y0 = (int)floorf(y);
    atomicMin(&g_zbuf[y0 * IMG_W + x0], __float_as_uint(z));
}

// ---------------------------------------------------------------------------
// Pass 2: visibility + bilinear scatter. rgbz via per-pixel v4 REDs (4 ops);
// w via the 2x2-blocked plane: 1 v4 / 2 v2 / 4 scalar REDs depending on the
// parity of (x0, y0). Same additions as before -> bit-equivalent result.
// Corner->weight map (reference): (x0,y0):wa (x1,y0):wc (x0,y1):wb (x1,y1):wd
// ---------------------------------------------------------------------------
__global__ void splat_kernel(const float* __restrict__ means,
                             const float* __restrict__ colors,
                             const float* __restrict__ vm,
                             const float* __restrict__ Km, int n)
{
    int i = blockIdx.x * blockDim.x + threadIdx.x;
    if (i >= n) return;
    float mx = means[3 * i], my = means[3 * i + 1], mz = means[3 * i + 2];
    float x, y, z;
    if (!project(vm, Km, mx, my, mz, x, y, z)) return;

    float x0f = floorf(x), y0f = floorf(y);
    int x0 = (int)x0f, y0 = (int)y0f;
    int pix = y0 * IMG_W + x0;

    float zref = __uint_as_float(g_zbuf[pix]);
    if (!(z <= zref + 0.05f)) return;

    float dx = x - x0f, dy = y - y0f;
    float wa = (1.f - dx) * (1.f - dy);
    float wb = dx * (1.f - dy);
    float wc = (1.f - dx) * dy;
    float wd = dx * dy;

    float r = sigmoidf(colors[3 * i]);
    float g = sigmoidf(colors[3 * i + 1]);
    float b = sigmoidf(colors[3 * i + 2]);

    int pb = pix + IMG_W;      // (x0, y1): wb
    int pc = pix + 1;          // (x1, y0): wc
    int pd = pix + IMG_W + 1;  // (x1, y1): wd

    atomicAdd(&g_buf4[pix], make_float4(r * wa, g * wa, b * wa, z * wa));
    atomicAdd(&g_buf4[pb],  make_float4(r * wb, g * wb, b * wb, z * wb));
    atomicAdd(&g_buf4[pc],  make_float4(r * wc, g * wc, b * wc, z * wc));
    atomicAdd(&g_buf4[pd],  make_float4(r * wd, g * wd, b * wd, z * wd));

    // w accumulation into 2x2-blocked plane
    int bx = x0 >> 1, by = y0 >> 1;
    int px = x0 & 1, py = y0 & 1;
    float* wp = &g_wplane[(by * WBLK + bx) * 4];
    if (px == 0) {
        if (py == 0) {
            // all 4 corners in one block: offs {0:wa, 1:wc, 2:wb, 3:wd}
            atomicAdd((float4*)wp, make_float4(wa, wc, wb, wd));
        } else {
            // top row (y0 odd) at offs {2,3}; bottom row (y1 even) in block below offs {0,1}
            atomicAdd((float2*)(wp + 2), make_float2(wa, wc));
            float* wq = &g_wplane[((by + 1) * WBLK + bx) * 4];
            atomicAdd((float2*)wq, make_float2(wb, wd));
        }
    } else {
        float* wq = &g_wplane[(by * WBLK + bx + 1) * 4];  // x1 block
        if (py == 0) {
            atomicAdd(wp + 1, wa);   // (x0,y0): off (0*2+1)
            atomicAdd(wp + 3, wb);   // (x0,y1): off (1*2+1)
            atomicAdd(wq + 0, wc);   // (x1,y0)
            atomicAdd(wq + 2, wd);   // (x1,y1)
        } else {
            atomicAdd(wp + 3, wa);   // (x0,y0): y0 odd, x0 odd -> off 3
            atomicAdd(wq + 2, wc);   // (x1,y0): off 2
            float* wr = &g_wplane[((by + 1) * WBLK + bx) * 4];
            float* ws = &g_wplane[((by + 1) * WBLK + bx + 1) * 4];
            atomicAdd(wr + 1, wb);   // (x0,y1): y1 even, x0 odd -> off 1
            atomicAdd(ws + 0, wd);   // (x1,y1): off 0
        }
    }
}

// ---------------------------------------------------------------------------
// Pass 3: normalize + write output. 2 horizontal pixels per thread:
// one float2 w read (contiguous in the blocked plane), two v4 rgbz reads,
// two v4 output writes — all fully coalesced.
// ---------------------------------------------------------------------------
__global__ void norm_kernel(float4* __restrict__ out)
{
    int t = blockIdx.x * blockDim.x + threadIdx.x;
    if (t >= HW / 2) return;
    int y  = t / WBLK;
    int xh = t - y * WBLK;          // horizontal pair index; x0 = 2*xh
    int pix = y * IMG_W + 2 * xh;

    float2 w2 = *(const float2*)&g_wplane[((y >> 1) * WBLK + xh) * 4 + (y & 1) * 2];
    float4 a0 = g_buf4[pix];
    float4 a1 = g_buf4[pix + 1];

    float inv0 = 1.f / (w2.x + 1e-6f);
    float inv1 = 1.f / (w2.y + 1e-6f);
    float4 o0, o1;
    o0.x = __saturatef(a0.x * inv0);
    o0.y = __saturatef(a0.y * inv0);
    o0.z = __saturatef(a0.z * inv0);
    o0.w = a0.w * inv0;
    o1.x = __saturatef(a1.x * inv1);
    o1.y = __saturatef(a1.y * inv1);
    o1.z = __saturatef(a1.z * inv1);
    o1.w = a1.w * inv1;
    out[pix]     = o0;
    out[pix + 1] = o1;
}

extern "C" void kernel_launch(void* const* d_in, const int* in_sizes, int n_in,
                              void* d_out, int out_size)
{
    const float* means  = (const float*)d_in[0];
    const float* colors = (const float*)d_in[1];
    // d_in[2] opacities, d_in[3] scales, d_in[4] quats: unused by reference output
    const float* vm = (const float*)d_in[5];
    const float* Km = (const float*)d_in[6];

    int n = in_sizes[0] / 3;

    const int B = 256;
    init_kernel<<<(HW4 + B - 1) / B, B>>>();
    zmin_kernel<<<(n + B - 1) / B, B>>>(means, vm, Km, n);
    splat_kernel<<<(n + B - 1) / B, B>>>(means, colors, vm, Km, n);
    norm_kernel<<<(HW / 2 + B - 1) / B, B>>>((float4*)d_out);
}

// round 14
// speedup vs baseline: 1.0561x; 1.0561x over previous
#include <cuda_runtime.h>
#include <math.h>

#define IMG_H 1080
#define IMG_W 1920
#define HW (IMG_H * IMG_W)
#define HW4 (HW / 4)
#define WBLK (IMG_W / 2)   // 960 2x2-blocks per block-row

// Scratch (no cudaMalloc allowed)
__device__ float4   g_buf4[HW];     // accumulated (r*w, g*w, b*w, z*w) per pixel
__device__ float    g_wplane[HW];   // accumulated w, 2x2-blocked:
                                    // idx(x,y) = ((y>>1)*WBLK + (x>>1))*4 + (y&1)*2 + (x&1)
__device__ unsigned g_zbuf[HW];     // z-buffer bits (positive floats: order-preserving)

// ---------------------------------------------------------------------------
// Init A: z-buffer only (must precede zmin's atomics). 12.5 MB.
// ---------------------------------------------------------------------------
__global__ void init_z_kernel() {
    int i = blockIdx.x * blockDim.x + threadIdx.x;
    if (i >= HW4) return;
    ((uint4*)g_zbuf)[i] = make_uint4(0x7f800000u, 0x7f800000u, 0x7f800000u, 0x7f800000u);
}

// EXACT arithmetic (discrete decisions downstream: floor, z-compare).
__device__ __forceinline__ bool project(
    const float* __restrict__ vm, const float* __restrict__ Km,
    float mx, float my, float mz,
    float& x, float& y, float& z)
{
    z = vm[8] * mx + vm[9] * my + vm[10] * mz + vm[11];
    if (!(z > 0.1f)) return false;
    float cxm = vm[0] * mx + vm[1] * my + vm[2] * mz + vm[3];
    float cym = vm[4] * mx + vm[5] * my + vm[6] * mz + vm[7];
    float fx = Km[0], cx = Km[2], fy = Km[4], cy = Km[5];
    x = cxm * fx / z + cx;
    y = cym * fy / z + cy;
    return (x >= 0.f) & (x < (float)(IMG_W - 1)) & (y >= 0.f) & (y < (float)(IMG_H - 1));
}

__device__ __forceinline__ float sigmoidf(float v) {
    return 1.f / (1.f + expf(-v));
}

// ---------------------------------------------------------------------------
// Pass 1: per-pixel z-min via atomicMin on float bits. The first HW4 threads
// ALSO zero the rgbz/w accumulators (different buffers than the atomics touch;
// completes before this kernel ends, i.e. before splat launches) — overlapping
// the 37.5 MB init with the projection/RED work instead of serializing it.
// ---------------------------------------------------------------------------
__global__ void zmin_kernel(const float* __restrict__ means,
                            const float* __restrict__ vm,
                            const float* __restrict__ Km, int n)
{
    int i = blockIdx.x * blockDim.x + threadIdx.x;

    if (i < HW4) {
        const float4 z4 = make_float4(0.f, 0.f, 0.f, 0.f);
        ((float4*)g_wplane)[i] = z4;
        g_buf4[i]           = z4;
        g_buf4[i + HW4]     = z4;
        g_buf4[i + 2*HW4]   = z4;
        g_buf4[i + 3*HW4]   = z4;
    }

    if (i >= n) return;
    float mx = means[3 * i], my = means[3 * i + 1], mz = means[3 * i + 2];
    float x, y, z;
    if (!project(vm, Km, mx, my, mz, x, y, z)) return;
    int x0 = (int)floorf(x);
    int y0 = (int)floorf(y);
    atomicMin(&g_zbuf[y0 * IMG_W + x0], __float_as_uint(z));
}

// ---------------------------------------------------------------------------
// Pass 2: visibility + bilinear scatter. rgbz via per-pixel v4 REDs; w via the
// 2x2-blocked plane (1 v4 / 2 v2 / 4 scalar REDs by parity). Bit-equivalent to
// scalar accumulation (same additions, atomic order is unordered anyway).
// Corner->weight map (reference): (x0,y0):wa (x1,y0):wc (x0,y1):wb (x1,y1):wd
// ---------------------------------------------------------------------------
__global__ void splat_kernel(const float* __restrict__ means,
                             const float* __restrict__ colors,
                             const float* __restrict__ vm,
                             const float* __restrict__ Km, int n)
{
    int i = blockIdx.x * blockDim.x + threadIdx.x;
    if (i >= n) return;
    float mx = means[3 * i], my = means[3 * i + 1], mz = means[3 * i + 2];
    float x, y, z;
    if (!project(vm, Km, mx, my, mz, x, y, z)) return;

    float x0f = floorf(x), y0f = floorf(y);
    int x0 = (int)x0f, y0 = (int)y0f;
    int pix = y0 * IMG_W + x0;

    float zref = __uint_as_float(g_zbuf[pix]);
    if (!(z <= zref + 0.05f)) return;

    float dx = x - x0f, dy = y - y0f;
    float wa = (1.f - dx) * (1.f - dy);
    float wb = dx * (1.f - dy);
    float wc = (1.f - dx) * dy;
    float wd = dx * dy;

    float r = sigmoidf(colors[3 * i]);
    float g = sigmoidf(colors[3 * i + 1]);
    float b = sigmoidf(colors[3 * i + 2]);

    int pb = pix + IMG_W;      // (x0, y1): wb
    int pc = pix + 1;          // (x1, y0): wc
    int pd = pix + IMG_W + 1;  // (x1, y1): wd

    atomicAdd(&g_buf4[pix], make_float4(r * wa, g * wa, b * wa, z * wa));
    atomicAdd(&g_buf4[pb],  make_float4(r * wb, g * wb, b * wb, z * wb));
    atomicAdd(&g_buf4[pc],  make_float4(r * wc, g * wc, b * wc, z * wc));
    atomicAdd(&g_buf4[pd],  make_float4(r * wd, g * wd, b * wd, z * wd));

    // w accumulation into 2x2-blocked plane
    int bx = x0 >> 1, by = y0 >> 1;
    int px = x0 & 1, py = y0 & 1;
    float* wp = &g_wplane[(by * WBLK + bx) * 4];
    if (px == 0) {
        if (py == 0) {
            atomicAdd((float4*)wp, make_float4(wa, wc, wb, wd));
        } else {
            atomicAdd((float2*)(wp + 2), make_float2(wa, wc));
            float* wq = &g_wplane[((by + 1) * WBLK + bx) * 4];
            atomicAdd((float2*)wq, make_float2(wb, wd));
        }
    } else {
        float* wq = &g_wplane[(by * WBLK + bx + 1) * 4];
        if (py == 0) {
            atomicAdd(wp + 1, wa);
            atomicAdd(wp + 3, wb);
            atomicAdd(wq + 0, wc);
            atomicAdd(wq + 2, wd);
        } else {
            atomicAdd(wp + 3, wa);
            atomicAdd(wq + 2, wc);
            float* wr = &g_wplane[((by + 1) * WBLK + bx) * 4];
            float* ws = &g_wplane[((by + 1) * WBLK + bx + 1) * 4];
            atomicAdd(wr + 1, wb);
            atomicAdd(ws + 0, wd);
        }
    }
}

// ---------------------------------------------------------------------------
// Pass 3: normalize + write output. 1 pixel/thread (measured fastest shape).
// ---------------------------------------------------------------------------
__global__ void norm_kernel(float4* __restrict__ out)
{
    int i = blockIdx.x * blockDim.x + threadIdx.x;
    if (i >= HW) return;
    int y = i / IMG_W;
    int x = i - y * IMG_W;
    float w = g_wplane[((y >> 1) * WBLK + (x >> 1)) * 4 + (y & 1) * 2 + (x & 1)];
    float4 acc = g_buf4[i];
    float inv = 1.f / (w + 1e-6f);
    float4 o;
    o.x = __saturatef(acc.x * inv);
    o.y = __saturatef(acc.y * inv);
    o.z = __saturatef(acc.z * inv);
    o.w = acc.w * inv;
    out[i] = o;
}

extern "C" void kernel_launch(void* const* d_in, const int* in_sizes, int n_in,
                              void* d_out, int out_size)
{
    const float* means  = (const float*)d_in[0];
    const float* colors = (const float*)d_in[1];
    // d_in[2] opacities, d_in[3] scales, d_in[4] quats: unused by reference output
    const float* vm = (const float*)d_in[5];
    const float* Km = (const float*)d_in[6];

    int n = in_sizes[0] / 3;
    int nz = (n > HW4) ? n : HW4;   // zmin grid also covers accumulator init

    const int B = 256;
    init_z_kernel<<<(HW4 + B - 1) / B, B>>>();
    zmin_kernel<<<(nz + B - 1) / B, B>>>(means, vm, Km, n);
    splat_kernel<<<(n + B - 1) / B, B>>>(means, colors, vm, Km, n);
    norm_kernel<<<(HW + B - 1) / B, B>>>((float4*)d_out);
}

// round 15
// speedup vs baseline: 1.5508x; 1.4684x over previous
#include <cuda_runtime.h>
#include <math.h>

#define IMG_H 1080
#define IMG_W 1920
#define HW (IMG_H * IMG_W)
#define HW4 (HW / 4)
#define WBLK (IMG_W / 2)   // 960 2x2-blocks per block-row

// Scratch (no cudaMalloc allowed)
__device__ float4   g_buf4[HW];     // accumulated (r*w, g*w, b*w, z*w) per pixel
__device__ float    g_wplane[HW];   // accumulated w, 2x2-blocked:
                                    // idx(x,y) = ((y>>1)*WBLK + (x>>1))*4 + (y&1)*2 + (x&1)
__device__ unsigned g_zbuf[HW];     // z-buffer bits (positive floats: order-preserving)

// ---------------------------------------------------------------------------
// Init A: z-buffer only (must precede zmin's atomics). 12.5 MB.
// ---------------------------------------------------------------------------
__global__ void init_z_kernel() {
    int i = blockIdx.x * blockDim.x + threadIdx.x;
    if (i >= HW4) return;
    ((uint4*)g_zbuf)[i] = make_uint4(0x7f800000u, 0x7f800000u, 0x7f800000u, 0x7f800000u);
}

// EXACT arithmetic for geometry: x/y/z feed discrete decisions (floor,
// z-compare) — fast-math here measurably breaks correctness (R7: 3.4e-3).
__device__ __forceinline__ bool project(
    const float* __restrict__ vm, const float* __restrict__ Km,
    float mx, float my, float mz,
    float& x, float& y, float& z)
{
    z = vm[8] * mx + vm[9] * my + vm[10] * mz + vm[11];
    if (!(z > 0.1f)) return false;
    float cxm = vm[0] * mx + vm[1] * my + vm[2] * mz + vm[3];
    float cym = vm[4] * mx + vm[5] * my + vm[6] * mz + vm[7];
    float fx = Km[0], cx = Km[2], fy = Km[4], cy = Km[5];
    x = cxm * fx / z + cx;     // exact div
    y = cym * fy / z + cy;     // exact div
    return (x >= 0.f) & (x < (float)(IMG_W - 1)) & (y >= 0.f) & (y < (float)(IMG_H - 1));
}

// FAST sigmoid: color values are smooth pass-through to the output (no
// discrete decisions). ~1e-6 relative error vs 1e-3 tolerance. Replaces a
// ~30-instruction exact expf+div sequence with ~5 instructions — splat is
// issue-bound on this.
__device__ __forceinline__ float sigmoidf(float v) {
    return __fdividef(1.f, 1.f + __expf(-v));
}

// ---------------------------------------------------------------------------
// Pass 1: per-pixel z-min via atomicMin on float bits. First HW4 threads also
// zero the rgbz/w accumulators (overlapped with projection/RED work; complete
// before splat launches).
// ---------------------------------------------------------------------------
__global__ void zmin_kernel(const float* __restrict__ means,
                            const float* __restrict__ vm,
                            const float* __restrict__ Km, int n)
{
    int i = blockIdx.x * blockDim.x + threadIdx.x;

    if (i < HW4) {
        const float4 z4 = make_float4(0.f, 0.f, 0.f, 0.f);
        ((float4*)g_wplane)[i] = z4;
        g_buf4[i]           = z4;
        g_buf4[i + HW4]     = z4;
        g_buf4[i + 2*HW4]   = z4;
        g_buf4[i + 3*HW4]   = z4;
    }

    if (i >= n) return;
    float mx = means[3 * i], my = means[3 * i + 1], mz = means[3 * i + 2];
    float x, y, z;
    if (!project(vm, Km, mx, my, mz, x, y, z)) return;
    int x0 = (int)floorf(x);
    int y0 = (int)floorf(y);
    atomicMin(&g_zbuf[y0 * IMG_W + x0], __float_as_uint(z));
}

// ---------------------------------------------------------------------------
// Pass 2: visibility + bilinear scatter. rgbz via per-pixel v4 REDs; w via the
// 2x2-blocked plane (1 v4 / 2 v2 / 4 scalar REDs by parity).
// Corner->weight map (reference): (x0,y0):wa (x1,y0):wc (x0,y1):wb (x1,y1):wd
// ---------------------------------------------------------------------------
__global__ void splat_kernel(const float* __restrict__ means,
                             const float* __restrict__ colors,
                             const float* __restrict__ vm,
                             const float* __restrict__ Km, int n)
{
    int i = blockIdx.x * blockDim.x + threadIdx.x;
    if (i >= n) return;
    float mx = means[3 * i], my = means[3 * i + 1], mz = means[3 * i + 2];
    float x, y, z;
    if (!project(vm, Km, mx, my, mz, x, y, z)) return;

    float x0f = floorf(x), y0f = floorf(y);
    int x0 = (int)x0f, y0 = (int)y0f;
    int pix = y0 * IMG_W + x0;

    float zref = __uint_as_float(g_zbuf[pix]);
    if (!(z <= zref + 0.05f)) return;

    float dx = x - x0f, dy = y - y0f;
    float wa = (1.f - dx) * (1.f - dy);
    float wb = dx * (1.f - dy);
    float wc = (1.f - dx) * dy;
    float wd = dx * dy;

    float r = sigmoidf(colors[3 * i]);
    float g = sigmoidf(colors[3 * i + 1]);
    float b = sigmoidf(colors[3 * i + 2]);

    int pb = pix + IMG_W;      // (x0, y1): wb
    int pc = pix + 1;          // (x1, y0): wc
    int pd = pix + IMG_W + 1;  // (x1, y1): wd

    atomicAdd(&g_buf4[pix], make_float4(r * wa, g * wa, b * wa, z * wa));
    atomicAdd(&g_buf4[pb],  make_float4(r * wb, g * wb, b * wb, z * wb));
    atomicAdd(&g_buf4[pc],  make_float4(r * wc, g * wc, b * wc, z * wc));
    atomicAdd(&g_buf4[pd],  make_float4(r * wd, g * wd, b * wd, z * wd));

    // w accumulation into 2x2-blocked plane
    int bx = x0 >> 1, by = y0 >> 1;
    int px = x0 & 1, py = y0 & 1;
    float* wp = &g_wplane[(by * WBLK + bx) * 4];
    if (px == 0) {
        if (py == 0) {
            atomicAdd((float4*)wp, make_float4(wa, wc, wb, wd));
        } else {
            atomicAdd((float2*)(wp + 2), make_float2(wa, wc));
            float* wq = &g_wplane[((by + 1) * WBLK + bx) * 4];
            atomicAdd((float2*)wq, make_float2(wb, wd));
        }
    } else {
        float* wq = &g_wplane[(by * WBLK + bx + 1) * 4];
        if (py == 0) {
            atomicAdd(wp + 1, wa);
            atomicAdd(wp + 3, wb);
            atomicAdd(wq + 0, wc);
            atomicAdd(wq + 2, wd);
        } else {
            atomicAdd(wp + 3, wa);
            atomicAdd(wq + 2, wc);
            float* wr = &g_wplane[((by + 1) * WBLK + bx) * 4];
            float* ws = &g_wplane[((by + 1) * WBLK + bx + 1) * 4];
            atomicAdd(wr + 1, wb);
            atomicAdd(ws + 0, wd);
        }
    }
}

// ---------------------------------------------------------------------------
// Pass 3: normalize + write output. Fast reciprocal: value-smooth (no discrete
// decisions), ~1e-7 relative error. 1 px/thread (measured fastest shape).
// ---------------------------------------------------------------------------
__global__ void norm_kernel(float4* __restrict__ out)
{
    int i = blockIdx.x * blockDim.x + threadIdx.x;
    if (i >= HW) return;
    int y = i / IMG_W;
    int x = i - y * IMG_W;
    float w = g_wplane[((y >> 1) * WBLK + (x >> 1)) * 4 + (y & 1) * 2 + (x & 1)];
    float4 acc = g_buf4[i];
    float inv = __fdividef(1.f, w + 1e-6f);
    float4 o;
    o.x = __saturatef(acc.x * inv);
    o.y = __saturatef(acc.y * inv);
    o.z = __saturatef(acc.z * inv);
    o.w = acc.w * inv;
    out[i] = o;
}

extern "C" void kernel_launch(void* const* d_in, const int* in_sizes, int n_in,
                              void* d_out, int out_size)
{
    const float* means  = (const float*)d_in[0];
    const float* colors = (const float*)d_in[1];
    // d_in[2] opacities, d_in[3] scales, d_in[4] quats: unused by reference output
    const float* vm = (const float*)d_in[5];
    const float* Km = (const float*)d_in[6];

    int n = in_sizes[0] / 3;
    int nz = (n > HW4) ? n : HW4;   // zmin grid also covers accumulator init

    const int B = 256;
    init_z_kernel<<<(HW4 + B - 1) / B, B>>>();
    zmin_kernel<<<(nz + B - 1) / B, B>>>(means, vm, Km, n);
    splat_kernel<<<(n + B - 1) / B, B>>>(means, colors, vm, Km, n);
    norm_kernel<<<(HW + B - 1) / B, B>>>((float4*)d_out);
}

// round 16
// speedup vs baseline: 1.5590x; 1.0053x over previous
#include <cuda_runtime.h>
#include <math.h>

#define IMG_H 1080
#define IMG_W 1920
#define HW (IMG_H * IMG_W)
#define HW4 (HW / 4)
#define WBLK (IMG_W / 2)   // 960 2x2-blocks per block-row

// Scratch (no cudaMalloc allowed). g_zbuf uses inverted keys so the "empty"
// value is 0: static zero-init at load + reset in norm_kernel give every
// invocation the identical starting state with NO dedicated init launch.
__device__ float4   g_buf4[HW];     // accumulated (r*w, g*w, b*w, z*w) per pixel
__device__ float    g_wplane[HW];   // accumulated w, 2x2-blocked:
                                    // idx(x,y) = ((y>>1)*WBLK + (x>>1))*4 + (y&1)*2 + (x&1)
__device__ unsigned g_zbuf[HW];     // INVERTED z bits: key = ~float_bits(z); 0 == "empty"
                                    // max(key) == min(z) exactly (z > 0). Untouched pixels
                                    // are never queried by splat (splat only reads pixels
                                    // zmin wrote).

// EXACT arithmetic for geometry: x/y/z feed discrete decisions (floor,
// z-compare) — fast-math here measurably breaks correctness (R7: 3.4e-3).
__device__ __forceinline__ bool project(
    const float* __restrict__ vm, const float* __restrict__ Km,
    float mx, float my, float mz,
    float& x, float& y, float& z)
{
    z = vm[8] * mx + vm[9] * my + vm[10] * mz + vm[11];
    if (!(z > 0.1f)) return false;
    float cxm = vm[0] * mx + vm[1] * my + vm[2] * mz + vm[3];
    float cym = vm[4] * mx + vm[5] * my + vm[6] * mz + vm[7];
    float fx = Km[0], cx = Km[2], fy = Km[4], cy = Km[5];
    x = cxm * fx / z + cx;     // exact div
    y = cym * fy / z + cy;     // exact div
    return (x >= 0.f) & (x < (float)(IMG_W - 1)) & (y >= 0.f) & (y < (float)(IMG_H - 1));
}

// FAST sigmoid: value-smooth (no discrete decisions); ~1e-6 rel error vs 1e-3
// tolerance. Measured: 142 -> 96.7us, rel_err 5.1e-8 -> 6.1e-8.
__device__ __forceinline__ float sigmoidf(float v) {
    return __fdividef(1.f, 1.f + __expf(-v));
}

// ---------------------------------------------------------------------------
// Pass 1: per-pixel z-min via atomicMax on inverted float bits. First HW4
// threads also zero the rgbz/w accumulators (overlapped with projection/RED
// work; complete before splat launches). Point stream read with __ldcs
// (evict-first) to keep L2 for the atomic working set.
// ---------------------------------------------------------------------------
__global__ void zmin_kernel(const float* __restrict__ means,
                            const float* __restrict__ vm,
                            const float* __restrict__ Km, int n)
{
    int i = blockIdx.x * blockDim.x + threadIdx.x;

    if (i < HW4) {
        const float4 z4 = make_float4(0.f, 0.f, 0.f, 0.f);
        ((float4*)g_wplane)[i] = z4;
        g_buf4[i]           = z4;
        g_buf4[i + HW4]     = z4;
        g_buf4[i + 2*HW4]   = z4;
        g_buf4[i + 3*HW4]   = z4;
    }

    if (i >= n) return;
    float mx = __ldcs(&means[3 * i]);
    float my = __ldcs(&means[3 * i + 1]);
    float mz = __ldcs(&means[3 * i + 2]);
    float x, y, z;
    if (!project(vm, Km, mx, my, mz, x, y, z)) return;
    int x0 = (int)floorf(x);
    int y0 = (int)floorf(y);
    atomicMax(&g_zbuf[y0 * IMG_W + x0], ~__float_as_uint(z));
}

// ---------------------------------------------------------------------------
// Pass 2: visibility + bilinear scatter. rgbz via per-pixel v4 REDs; w via the
// 2x2-blocked plane (1 v4 / 2 v2 / 4 scalar REDs by parity). Point streams via
// __ldcs. Corner->weight map (reference): (x0,y0):wa (x1,y0):wc (x0,y1):wb
// (x1,y1):wd.
// ---------------------------------------------------------------------------
__global__ void splat_kernel(const float* __restrict__ means,
                             const float* __restrict__ colors,
                             const float* __restrict__ vm,
                             const float* __restrict__ Km, int n)
{
    int i = blockIdx.x * blockDim.x + threadIdx.x;
    if (i >= n) return;
    float mx = __ldcs(&means[3 * i]);
    float my = __ldcs(&means[3 * i + 1]);
    float mz = __ldcs(&means[3 * i + 2]);
    float x, y, z;
    if (!project(vm, Km, mx, my, mz, x, y, z)) return;

    float x0f = floorf(x), y0f = floorf(y);
    int x0 = (int)x0f, y0 = (int)y0f;
    int pix = y0 * IMG_W + x0;

    float zref = __uint_as_float(~g_zbuf[pix]);
    if (!(z <= zref + 0.05f)) return;

    float dx = x - x0f, dy = y - y0f;
    float wa = (1.f - dx) * (1.f - dy);
    float wb = dx * (1.f - dy);
    float wc = (1.f - dx) * dy;
    float wd = dx * dy;

    float r = sigmoidf(__ldcs(&colors[3 * i]));
    float g = sigmoidf(__ldcs(&colors[3 * i + 1]));
    float b = sigmoidf(__ldcs(&colors[3 * i + 2]));

    int pb = pix + IMG_W;      // (x0, y1): wb
    int pc = pix + 1;          // (x1, y0): wc
    int pd = pix + IMG_W + 1;  // (x1, y1): wd

    atomicAdd(&g_buf4[pix], make_float4(r * wa, g * wa, b * wa, z * wa));
    atomicAdd(&g_buf4[pb],  make_float4(r * wb, g * wb, b * wb, z * wb));
    atomicAdd(&g_buf4[pc],  make_float4(r * wc, g * wc, b * wc, z * wc));
    atomicAdd(&g_buf4[pd],  make_float4(r * wd, g * wd, b * wd, z * wd));

    // w accumulation into 2x2-blocked plane
    int bx = x0 >> 1, by = y0 >> 1;
    int px = x0 & 1, py = y0 & 1;
    float* wp = &g_wplane[(by * WBLK + bx) * 4];
    if (px == 0) {
        if (py == 0) {
            atomicAdd((float4*)wp, make_float4(wa, wc, wb, wd));
        } else {
            atomicAdd((float2*)(wp + 2), make_float2(wa, wc));
            float* wq = &g_wplane[((by + 1) * WBLK + bx) * 4];
            atomicAdd((float2*)wq, make_float2(wb, wd));
        }
    } else {
        float* wq = &g_wplane[(by * WBLK + bx + 1) * 4];
        if (py == 0) {
            atomicAdd(wp + 1, wa);
            atomicAdd(wp + 3, wb);
            atomicAdd(wq + 0, wc);
            atomicAdd(wq + 2, wd);
        } else {
            atomicAdd(wp + 3, wa);
            atomicAdd(wq + 2, wc);
            float* wr = &g_wplane[((by + 1) * WBLK + bx) * 4];
            float* ws = &g_wplane[((by + 1) * WBLK + bx + 1) * 4];
            atomicAdd(wr + 1, wb);
            atomicAdd(ws + 0, wd);
        }
    }
}

// ---------------------------------------------------------------------------
// Pass 3: normalize + write output, and reset the z-buffer to the all-zeros
// "empty" state for the next invocation. 1 px/thread (measured fastest shape).
// ---------------------------------------------------------------------------
__global__ void norm_kernel(float4* __restrict__ out)
{
    int i = blockIdx.x * blockDim.x + threadIdx.x;
    if (i >= HW) return;
    int y = i / IMG_W;
    int x = i - y * IMG_W;
    float w = g_wplane[((y >> 1) * WBLK + (x >> 1)) * 4 + (y & 1) * 2 + (x & 1)];
    float4 acc = g_buf4[i];

    g_zbuf[i] = 0u;   // restore "empty" invariant (accumulators reset in zmin)

    float inv = __fdividef(1.f, w + 1e-6f);
    float4 o;
    o.x = __saturatef(acc.x * inv);
    o.y = __saturatef(acc.y * inv);
    o.z = __saturatef(acc.z * inv);
    o.w = acc.w * inv;
    out[i] = o;
}

extern "C" void kernel_launch(void* const* d_in, const int* in_sizes, int n_in,
                              void* d_out, int out_size)
{
    const float* means  = (const float*)d_in[0];
    const float* colors = (const float*)d_in[1];
    // d_in[2] opacities, d_in[3] scales, d_in[4] quats: unused by reference output
    const float* vm = (const float*)d_in[5];
    const float* Km = (const float*)d_in[6];

    int n = in_sizes[0] / 3;
    int nz = (n > HW4) ? n : HW4;   // zmin grid also covers accumulator init

    const int B = 256;
    zmin_kernel<<<(nz + B - 1) / B, B>>>(means, vm, Km, n);
    splat_kernel<<<(n + B - 1) / B, B>>>(means, colors, vm, Km, n);
    norm_kernel<<<(HW + B - 1) / B, B>>>((float4*)d_out);
}